// round 4
// baseline (speedup 1.0000x reference)
#include <cuda_runtime.h>
#include <cstdint>

#define NN 100000
#define EE 1600000
#define FIN 128
#define HID 64
#define NCLS 16

#define SCAN_B 512
#define SCAN_NB ((NN + SCAN_B - 1) / SCAN_B)   // 196

// ---- scratch (__device__ globals: allocation-free rule) ----
__device__ __align__(16) int   g_cnt[NN];
__device__ __align__(16) int   g_rowptr[NN + 1];
__device__ __align__(16) int   g_cursor[NN];
__device__ __align__(16) int   g_bsum[SCAN_NB];
__device__ __align__(16) float g_dinv[NN];
__device__ __align__(16) int2  g_csr[EE];          // {src, float_bits(w)}
__device__ __align__(16) float g_h[(size_t)NN * HID];
__device__ __align__(16) float g_x1[(size_t)NN * HID];

static inline int cdiv(long long a, int b) { return (int)((a + b - 1) / b); }

// ---------------------------------------------------------------------------
// CSR build
// ---------------------------------------------------------------------------
__global__ void k_zero_cnt() {
    int i = blockIdx.x * blockDim.x + threadIdx.x;
    if (i < NN) g_cnt[i] = 0;
}

// 4 edges per thread, int4 dst reads
__global__ void k_hist(const int* __restrict__ ei) {
    int t = blockIdx.x * blockDim.x + threadIdx.x;
    if (t >= EE / 4) return;
    int4 d = *reinterpret_cast<const int4*>(ei + EE + 4 * t);
    atomicAdd(&g_cnt[d.x], 1);
    atomicAdd(&g_cnt[d.y], 1);
    atomicAdd(&g_cnt[d.z], 1);
    atomicAdd(&g_cnt[d.w], 1);
}

// warp-shuffle block scan (exclusive), 512 threads
__global__ void k_scan1() {
    __shared__ int wsum[16];
    int i = blockIdx.x * SCAN_B + threadIdx.x;
    int lane = threadIdx.x & 31;
    int wid = threadIdx.x >> 5;
    int v = (i < NN) ? g_cnt[i] : 0;
    int s = v;
#pragma unroll
    for (int o = 1; o < 32; o <<= 1) {
        int t = __shfl_up_sync(0xffffffffu, s, o);
        if (lane >= o) s += t;
    }
    if (lane == 31) wsum[wid] = s;
    __syncthreads();
    if (wid == 0) {
        int ws = (lane < 16) ? wsum[lane] : 0;
#pragma unroll
        for (int o = 1; o < 16; o <<= 1) {
            int t = __shfl_up_sync(0xffffffffu, ws, o);
            if (lane >= o) ws += t;
        }
        if (lane < 16) wsum[lane] = ws;
    }
    __syncthreads();
    int wpre = (wid > 0) ? wsum[wid - 1] : 0;
    int incl = s + wpre;
    if (i < NN) g_rowptr[i] = incl - v;                 // exclusive
    if (threadIdx.x == SCAN_B - 1) g_bsum[blockIdx.x] = incl;
}

// scan over 196 block sums: 7 warps, shuffle-based
__global__ void k_scan2() {
    __shared__ int wsum[8];
    int t = threadIdx.x;           // 224 threads
    int lane = t & 31;
    int wid = t >> 5;
    int v = (t < SCAN_NB) ? g_bsum[t] : 0;
    int s = v;
#pragma unroll
    for (int o = 1; o < 32; o <<= 1) {
        int u = __shfl_up_sync(0xffffffffu, s, o);
        if (lane >= o) s += u;
    }
    if (lane == 31) wsum[wid] = s;
    __syncthreads();
    if (wid == 0) {
        int ws = (lane < 7) ? wsum[lane] : 0;
#pragma unroll
        for (int o = 1; o < 8; o <<= 1) {
            int u = __shfl_up_sync(0xffffffffu, ws, o);
            if (lane >= o) ws += u;
        }
        if (lane < 7) wsum[lane] = ws;
    }
    __syncthreads();
    int wpre = (wid > 0) ? wsum[wid - 1] : 0;
    if (t < SCAN_NB) g_bsum[t] = s + wpre - v;          // exclusive
}

__global__ void k_scan3() {
    int i = blockIdx.x * blockDim.x + threadIdx.x;
    if (i >= NN) return;
    int rp = g_rowptr[i] + g_bsum[i / SCAN_B];
    g_rowptr[i] = rp;
    g_cursor[i] = rp;
    g_dinv[i] = rsqrtf(1.0f + (float)g_cnt[i]);         // deg + self-loop
    if (i == 0) g_rowptr[NN] = EE;
}

// 2 edges per thread, int2 reads of src/dst halves
__global__ void k_fill(const int* __restrict__ ei) {
    int t = blockIdx.x * blockDim.x + threadIdx.x;
    if (t >= EE / 2) return;
    int2 s2 = *reinterpret_cast<const int2*>(ei + 2 * t);
    int2 d2 = *reinterpret_cast<const int2*>(ei + EE + 2 * t);
    int p0 = atomicAdd(&g_cursor[d2.x], 1);
    g_csr[p0] = make_int2(s2.x, __float_as_int(g_dinv[s2.x] * g_dinv[d2.x]));
    int p1 = atomicAdd(&g_cursor[d2.y], 1);
    g_csr[p1] = make_int2(s2.y, __float_as_int(g_dinv[s2.y] * g_dinv[d2.y]));
}

// ---------------------------------------------------------------------------
// GEMM: g_h = X @ W. One thread per node, float4 smem W reads.
// ---------------------------------------------------------------------------
template <int K, int O>
__global__ void k_gemm(const float* __restrict__ X, const float* __restrict__ W) {
    __shared__ __align__(16) float Ws[K * O];
    for (int i = threadIdx.x; i < K * O; i += blockDim.x) Ws[i] = W[i];
    __syncthreads();

    int node = blockIdx.x * blockDim.x + threadIdx.x;
    if (node >= NN) return;

    float4 acc[O / 4];
#pragma unroll
    for (int o = 0; o < O / 4; ++o) acc[o] = make_float4(0.f, 0.f, 0.f, 0.f);

    const float4* xr = reinterpret_cast<const float4*>(X + (size_t)node * K);
    for (int k4 = 0; k4 < K / 4; ++k4) {
        float4 xv = xr[k4];
        float xk[4] = {xv.x, xv.y, xv.z, xv.w};
#pragma unroll
        for (int kk = 0; kk < 4; ++kk) {
            const float4* wr = reinterpret_cast<const float4*>(&Ws[(k4 * 4 + kk) * O]);
#pragma unroll
            for (int o = 0; o < O / 4; ++o) {
                float4 w = wr[o];
                acc[o].x = fmaf(xk[kk], w.x, acc[o].x);
                acc[o].y = fmaf(xk[kk], w.y, acc[o].y);
                acc[o].z = fmaf(xk[kk], w.z, acc[o].z);
                acc[o].w = fmaf(xk[kk], w.w, acc[o].w);
            }
        }
    }

    float4* hp = reinterpret_cast<float4*>(&g_h[(size_t)node * O]);
#pragma unroll
    for (int o = 0; o < O / 4; ++o) hp[o] = acc[o];
}

// ---------------------------------------------------------------------------
// Gather (O=64): ONE node per warp, 2 edge-slots x 16 lanes x float4.
// Halves loop trips vs 2-node/warp and doubles gather MLP.
// ---------------------------------------------------------------------------
template <bool RELU>
__global__ void k_gather64(const float* __restrict__ b, float* __restrict__ out) {
    int node = blockIdx.x * (blockDim.x >> 5) + (threadIdx.x >> 5);
    if (node >= NN) return;
    int lane = threadIdx.x & 31;
    int eslot = lane >> 4;
    int fl = lane & 15;

    int beg = g_rowptr[node];
    int cnt = g_rowptr[node + 1] - beg;

    float4 acc = make_float4(0.f, 0.f, 0.f, 0.f);
#pragma unroll 4
    for (int k = eslot; k < cnt; k += 2) {
        int2 c = __ldg(&g_csr[beg + k]);
        float w = __int_as_float(c.y);
        float4 hv = *reinterpret_cast<const float4*>(&g_h[(size_t)c.x * HID + 4 * fl]);
        acc.x = fmaf(hv.x, w, acc.x);
        acc.y = fmaf(hv.y, w, acc.y);
        acc.z = fmaf(hv.z, w, acc.z);
        acc.w = fmaf(hv.w, w, acc.w);
    }

    // combine the two edge-slots
    acc.x += __shfl_xor_sync(0xffffffffu, acc.x, 16);
    acc.y += __shfl_xor_sync(0xffffffffu, acc.y, 16);
    acc.z += __shfl_xor_sync(0xffffffffu, acc.z, 16);
    acc.w += __shfl_xor_sync(0xffffffffu, acc.w, 16);

    if (eslot == 0) {
        float di = g_dinv[node];
        float s2 = di * di;
        float4 hv = *reinterpret_cast<const float4*>(&g_h[(size_t)node * HID + 4 * fl]);
        float4 bv = *reinterpret_cast<const float4*>(&b[4 * fl]);
        acc.x = fmaf(hv.x, s2, acc.x) + bv.x;
        acc.y = fmaf(hv.y, s2, acc.y) + bv.y;
        acc.z = fmaf(hv.z, s2, acc.z) + bv.z;
        acc.w = fmaf(hv.w, s2, acc.w) + bv.w;
        if (RELU) {
            acc.x = fmaxf(acc.x, 0.f);
            acc.y = fmaxf(acc.y, 0.f);
            acc.z = fmaxf(acc.z, 0.f);
            acc.w = fmaxf(acc.w, 0.f);
        }
        *reinterpret_cast<float4*>(&out[(size_t)node * HID + 4 * fl]) = acc;
    }
}

// ---------------------------------------------------------------------------
// Gather (O=16): ONE node per warp, 2 edge-slots x 16 lanes x 1 float.
// ---------------------------------------------------------------------------
template <bool RELU>
__global__ void k_gather16(const float* __restrict__ b, float* __restrict__ out) {
    int node = blockIdx.x * (blockDim.x >> 5) + (threadIdx.x >> 5);
    if (node >= NN) return;
    int lane = threadIdx.x & 31;
    int eslot = lane >> 4;
    int fl = lane & 15;

    int beg = g_rowptr[node];
    int cnt = g_rowptr[node + 1] - beg;

    float acc = 0.f;
#pragma unroll 4
    for (int k = eslot; k < cnt; k += 2) {
        int2 c = __ldg(&g_csr[beg + k]);
        float w = __int_as_float(c.y);
        acc = fmaf(g_h[(size_t)c.x * NCLS + fl], w, acc);
    }

    acc += __shfl_xor_sync(0xffffffffu, acc, 16);

    if (eslot == 0) {
        float di = g_dinv[node];
        acc = fmaf(g_h[(size_t)node * NCLS + fl], di * di, acc) + __ldg(&b[fl]);
        if (RELU) acc = fmaxf(acc, 0.f);
        out[(size_t)node * NCLS + fl] = acc;
    }
}

// ---------------------------------------------------------------------------
// Launch
// ---------------------------------------------------------------------------
extern "C" void kernel_launch(void* const* d_in, const int* in_sizes, int n_in,
                              void* d_out, int out_size) {
    const float* x  = (const float*)d_in[0];
    const int*   ei = (const int*)  d_in[1];
    const float* W1 = (const float*)d_in[2];
    const float* b1 = (const float*)d_in[3];
    const float* Wh = (const float*)d_in[4];
    const float* bh = (const float*)d_in[5];
    const float* W2 = (const float*)d_in[6];
    const float* b2 = (const float*)d_in[7];

    float* logits = (float*)d_out;                       // [N, 16]
    float* latent = (float*)d_out + (size_t)NN * NCLS;   // [N, 64]

    float* x1;
    cudaGetSymbolAddress((void**)&x1, g_x1);

    const int T = 256;
    const int GB = cdiv(NN, 8);   // 1 node/warp, 8 warps/block

    // CSR build
    k_zero_cnt<<<cdiv(NN, T), T>>>();
    k_hist<<<cdiv(EE / 4, T), T>>>(ei);
    k_scan1<<<SCAN_NB, SCAN_B>>>();
    k_scan2<<<1, 224>>>();
    k_scan3<<<cdiv(NN, T), T>>>();
    k_fill<<<cdiv(EE / 2, T), T>>>(ei);

    // layer 1: 128 -> 64, relu
    k_gemm<FIN, HID><<<cdiv(NN, 128), 128>>>(x, W1);
    k_gather64<true><<<GB, T>>>(b1, x1);

    // layer 2: 64 -> 64, relu -> latent
    k_gemm<HID, HID><<<cdiv(NN, 128), 128>>>(x1, Wh);
    k_gather64<true><<<GB, T>>>(bh, latent);

    // layer 3: 64 -> 16, logits
    k_gemm<HID, NCLS><<<cdiv(NN, 128), 128>>>(latent, W2);
    k_gather16<false><<<GB, T>>>(b2, logits);
}

// round 5
// speedup vs baseline: 1.1353x; 1.1353x over previous
#include <cuda_runtime.h>
#include <cuda_fp16.h>
#include <cstdint>

#define NN 100000
#define EE 1600000
#define FIN 128
#define HID 64
#define NCLS 16

#define SCAN_B 512
#define SCAN_NB ((NN + SCAN_B - 1) / SCAN_B)   // 196

// ---- scratch (__device__ globals: allocation-free rule) ----
__device__ __align__(16) int    g_cnt[NN];
__device__ __align__(16) int    g_rowptr[NN + 1];
__device__ __align__(16) int    g_cursor[NN];
__device__ __align__(16) int    g_bsum[SCAN_NB];
__device__ __align__(16) float  g_dinv[NN];
__device__ __align__(16) int2   g_csr[EE];            // {src, float_bits(w)}
__device__ __align__(16) __half g_h16[(size_t)NN * HID];   // fp16 GEMM output (gathered)
__device__ __align__(16) float  g_x1[(size_t)NN * HID];

static inline int cdiv(long long a, int b) { return (int)((a + b - 1) / b); }

// ---------------------------------------------------------------------------
// CSR build
// ---------------------------------------------------------------------------
__global__ void k_zero_cnt() {
    int i = blockIdx.x * blockDim.x + threadIdx.x;
    if (i < NN) g_cnt[i] = 0;
}

__global__ void k_hist(const int* __restrict__ ei) {
    int t = blockIdx.x * blockDim.x + threadIdx.x;
    if (t >= EE / 4) return;
    int4 d = *reinterpret_cast<const int4*>(ei + EE + 4 * t);
    atomicAdd(&g_cnt[d.x], 1);
    atomicAdd(&g_cnt[d.y], 1);
    atomicAdd(&g_cnt[d.z], 1);
    atomicAdd(&g_cnt[d.w], 1);
}

// warp-shuffle block scan (exclusive), 512 threads
__global__ void k_scan1() {
    __shared__ int wsum[16];
    int i = blockIdx.x * SCAN_B + threadIdx.x;
    int lane = threadIdx.x & 31;
    int wid = threadIdx.x >> 5;
    int v = (i < NN) ? g_cnt[i] : 0;
    int s = v;
#pragma unroll
    for (int o = 1; o < 32; o <<= 1) {
        int t = __shfl_up_sync(0xffffffffu, s, o);
        if (lane >= o) s += t;
    }
    if (lane == 31) wsum[wid] = s;
    __syncthreads();
    if (wid == 0) {
        int ws = (lane < 16) ? wsum[lane] : 0;
#pragma unroll
        for (int o = 1; o < 16; o <<= 1) {
            int t = __shfl_up_sync(0xffffffffu, ws, o);
            if (lane >= o) ws += t;
        }
        if (lane < 16) wsum[lane] = ws;
    }
    __syncthreads();
    int wpre = (wid > 0) ? wsum[wid - 1] : 0;
    int incl = s + wpre;
    if (i < NN) g_rowptr[i] = incl - v;                 // exclusive
    if (threadIdx.x == SCAN_B - 1) g_bsum[blockIdx.x] = incl;
}

__global__ void k_scan2() {
    __shared__ int wsum[8];
    int t = threadIdx.x;           // 224 threads
    int lane = t & 31;
    int wid = t >> 5;
    int v = (t < SCAN_NB) ? g_bsum[t] : 0;
    int s = v;
#pragma unroll
    for (int o = 1; o < 32; o <<= 1) {
        int u = __shfl_up_sync(0xffffffffu, s, o);
        if (lane >= o) s += u;
    }
    if (lane == 31) wsum[wid] = s;
    __syncthreads();
    if (wid == 0) {
        int ws = (lane < 7) ? wsum[lane] : 0;
#pragma unroll
        for (int o = 1; o < 8; o <<= 1) {
            int u = __shfl_up_sync(0xffffffffu, ws, o);
            if (lane >= o) ws += u;
        }
        if (lane < 7) wsum[lane] = ws;
    }
    __syncthreads();
    int wpre = (wid > 0) ? wsum[wid - 1] : 0;
    if (t < SCAN_NB) g_bsum[t] = s + wpre - v;          // exclusive
}

__global__ void k_scan3() {
    int i = blockIdx.x * blockDim.x + threadIdx.x;
    if (i >= NN) return;
    int rp = g_rowptr[i] + g_bsum[i / SCAN_B];
    g_rowptr[i] = rp;
    g_cursor[i] = rp;
    g_dinv[i] = rsqrtf(1.0f + (float)g_cnt[i]);         // deg + self-loop
    if (i == 0) g_rowptr[NN] = EE;
}

// one edge per thread (R3 form — independent atomics)
__global__ void k_fill(const int* __restrict__ ei) {
    int e = blockIdx.x * blockDim.x + threadIdx.x;
    if (e >= EE) return;
    int s = ei[e];
    int d = ei[EE + e];
    int pos = atomicAdd(&g_cursor[d], 1);
    g_csr[pos] = make_int2(s, __float_as_int(g_dinv[s] * g_dinv[d]));
}

// ---------------------------------------------------------------------------
// GEMM: g_h16 = fp16(X @ W). One thread per node; fp32 accumulate.
// ---------------------------------------------------------------------------
template <int K, int O>
__global__ void k_gemm(const float* __restrict__ X, const float* __restrict__ W) {
    __shared__ __align__(16) float Ws[K * O];
    for (int i = threadIdx.x; i < K * O; i += blockDim.x) Ws[i] = W[i];
    __syncthreads();

    int node = blockIdx.x * blockDim.x + threadIdx.x;
    if (node >= NN) return;

    float4 acc[O / 4];
#pragma unroll
    for (int o = 0; o < O / 4; ++o) acc[o] = make_float4(0.f, 0.f, 0.f, 0.f);

    const float4* xr = reinterpret_cast<const float4*>(X + (size_t)node * K);
    for (int k4 = 0; k4 < K / 4; ++k4) {
        float4 xv = xr[k4];
        float xk[4] = {xv.x, xv.y, xv.z, xv.w};
#pragma unroll
        for (int kk = 0; kk < 4; ++kk) {
            const float4* wr = reinterpret_cast<const float4*>(&Ws[(k4 * 4 + kk) * O]);
#pragma unroll
            for (int o = 0; o < O / 4; ++o) {
                float4 w = wr[o];
                acc[o].x = fmaf(xk[kk], w.x, acc[o].x);
                acc[o].y = fmaf(xk[kk], w.y, acc[o].y);
                acc[o].z = fmaf(xk[kk], w.z, acc[o].z);
                acc[o].w = fmaf(xk[kk], w.w, acc[o].w);
            }
        }
    }

    // pack to fp16 and store (O/2 half2 = O*2 bytes, vectorized as uint4s)
    __align__(16) __half2 hbuf[O / 2];
#pragma unroll
    for (int o = 0; o < O / 4; ++o) {
        hbuf[2 * o]     = __floats2half2_rn(acc[o].x, acc[o].y);
        hbuf[2 * o + 1] = __floats2half2_rn(acc[o].z, acc[o].w);
    }
    uint4* dst = reinterpret_cast<uint4*>(&g_h16[(size_t)node * O]);
    const uint4* srcb = reinterpret_cast<const uint4*>(hbuf);
#pragma unroll
    for (int i = 0; i < (O * 2) / 16; ++i) dst[i] = srcb[i];
}

// ---------------------------------------------------------------------------
// Gather (O=64): 2 nodes per warp, 16 lanes x 4 halves (uint2 load) per node.
// Joint max-deg loop (predicated); uniform int2 CSR loads. fp32 accumulate.
// ---------------------------------------------------------------------------
template <bool RELU>
__global__ void k_gather64(const float* __restrict__ b, float* __restrict__ out) {
    int warp = blockIdx.x * (blockDim.x >> 5) + (threadIdx.x >> 5);
    int half = (threadIdx.x >> 4) & 1;
    int node = warp * 2 + half;          // NN even; grid sized exactly
    int lane = threadIdx.x & 15;

    int beg = g_rowptr[node];
    int cnt = g_rowptr[node + 1] - beg;
    int ocnt = __shfl_xor_sync(0xffffffffu, cnt, 16);
    int maxcnt = cnt > ocnt ? cnt : ocnt;

    float4 acc = make_float4(0.f, 0.f, 0.f, 0.f);
#pragma unroll 2
    for (int k = 0; k < maxcnt; ++k) {
        if (k < cnt) {
            int2 c = __ldg(&g_csr[beg + k]);
            float w = __int_as_float(c.y);
            uint2 u = *reinterpret_cast<const uint2*>(&g_h16[(size_t)c.x * HID + 4 * lane]);
            float2 f01 = __half22float2(*reinterpret_cast<__half2*>(&u.x));
            float2 f23 = __half22float2(*reinterpret_cast<__half2*>(&u.y));
            acc.x = fmaf(f01.x, w, acc.x);
            acc.y = fmaf(f01.y, w, acc.y);
            acc.z = fmaf(f23.x, w, acc.z);
            acc.w = fmaf(f23.y, w, acc.w);
        }
    }

    float di = g_dinv[node];
    float s2 = di * di;
    uint2 u = *reinterpret_cast<const uint2*>(&g_h16[(size_t)node * HID + 4 * lane]);
    float2 f01 = __half22float2(*reinterpret_cast<__half2*>(&u.x));
    float2 f23 = __half22float2(*reinterpret_cast<__half2*>(&u.y));
    float4 bv = *reinterpret_cast<const float4*>(&b[4 * lane]);
    acc.x = fmaf(f01.x, s2, acc.x) + bv.x;
    acc.y = fmaf(f01.y, s2, acc.y) + bv.y;
    acc.z = fmaf(f23.x, s2, acc.z) + bv.z;
    acc.w = fmaf(f23.y, s2, acc.w) + bv.w;
    if (RELU) {
        acc.x = fmaxf(acc.x, 0.f);
        acc.y = fmaxf(acc.y, 0.f);
        acc.z = fmaxf(acc.z, 0.f);
        acc.w = fmaxf(acc.w, 0.f);
    }
    *reinterpret_cast<float4*>(&out[(size_t)node * HID + 4 * lane]) = acc;
}

// ---------------------------------------------------------------------------
// Gather (O=16): 2 nodes per warp, 16 lanes x 1 half per node.
// ---------------------------------------------------------------------------
template <bool RELU>
__global__ void k_gather16(const float* __restrict__ b, float* __restrict__ out) {
    int warp = blockIdx.x * (blockDim.x >> 5) + (threadIdx.x >> 5);
    int half = (threadIdx.x >> 4) & 1;
    int node = warp * 2 + half;
    int lane = threadIdx.x & 15;

    int beg = g_rowptr[node];
    int cnt = g_rowptr[node + 1] - beg;
    int ocnt = __shfl_xor_sync(0xffffffffu, cnt, 16);
    int maxcnt = cnt > ocnt ? cnt : ocnt;

    float acc = 0.f;
#pragma unroll 2
    for (int k = 0; k < maxcnt; ++k) {
        if (k < cnt) {
            int2 c = __ldg(&g_csr[beg + k]);
            float w = __int_as_float(c.y);
            float hv = __half2float(g_h16[(size_t)c.x * NCLS + lane]);
            acc = fmaf(hv, w, acc);
        }
    }

    float di = g_dinv[node];
    float hv = __half2float(g_h16[(size_t)node * NCLS + lane]);
    acc = fmaf(hv, di * di, acc) + __ldg(&b[lane]);
    if (RELU) acc = fmaxf(acc, 0.f);
    out[(size_t)node * NCLS + lane] = acc;
}

// ---------------------------------------------------------------------------
// Launch
// ---------------------------------------------------------------------------
extern "C" void kernel_launch(void* const* d_in, const int* in_sizes, int n_in,
                              void* d_out, int out_size) {
    const float* x  = (const float*)d_in[0];
    const int*   ei = (const int*)  d_in[1];
    const float* W1 = (const float*)d_in[2];
    const float* b1 = (const float*)d_in[3];
    const float* Wh = (const float*)d_in[4];
    const float* bh = (const float*)d_in[5];
    const float* W2 = (const float*)d_in[6];
    const float* b2 = (const float*)d_in[7];

    float* logits = (float*)d_out;                       // [N, 16]
    float* latent = (float*)d_out + (size_t)NN * NCLS;   // [N, 64]

    float* x1;
    cudaGetSymbolAddress((void**)&x1, g_x1);

    const int T = 256;
    const int GB = cdiv(NN, 16);   // 2 nodes/warp, 8 warps/block

    // CSR build
    k_zero_cnt<<<cdiv(NN, T), T>>>();
    k_hist<<<cdiv(EE / 4, T), T>>>(ei);
    k_scan1<<<SCAN_NB, SCAN_B>>>();
    k_scan2<<<1, 224>>>();
    k_scan3<<<cdiv(NN, T), T>>>();
    k_fill<<<cdiv(EE, T), T>>>(ei);

    // layer 1: 128 -> 64, relu
    k_gemm<FIN, HID><<<cdiv(NN, 128), 128>>>(x, W1);
    k_gather64<true><<<GB, T>>>(b1, x1);

    // layer 2: 64 -> 64, relu -> latent
    k_gemm<HID, HID><<<cdiv(NN, 128), 128>>>(x1, Wh);
    k_gather64<true><<<GB, T>>>(bh, latent);

    // layer 3: 64 -> 16, logits
    k_gemm<HID, NCLS><<<cdiv(NN, 128), 128>>>(latent, W2);
    k_gather16<false><<<GB, T>>>(b2, logits);
}